// round 16
// baseline (speedup 1.0000x reference)
#include <cuda_runtime.h>

#define NN 50000
#define EE 800000
#define DD 64
#define GG 64

#define SCAN_B 256
#define NSB ((NN + SCAN_B - 1) / SCAN_B)   // 196 blocks

// ---------------- scratch (device globals; accessed ONLY by symbol in device code)
__device__ int   d_is64 = 1;           // write-once 1->0 (deterministic across replays)
__device__ int   d_batch[NN];
__device__ int   d_deg[NN];
__device__ int   d_rowptr[NN + 1];
__device__ int   d_cursor[NN];
__device__ int2  d_csr[EE];            // (col, edge_attr float bits)
__device__ int   d_bsum[NSB];
__device__ int   d_degmaxbits[GG];     // per-graph max degree, float bits (degree >= 0)
__device__ float d_e0[NN * DD];        // x_emb ping
__device__ float d_e1[NN * DD];        // x_emb pong
__device__ float d_xagg[NN * DD];      // per-layer gathered mean
__device__ float d_nein[NN * DD];      // [0:62] relu node_edge embed, [63] degree_norm
__device__ float d_xaggemb[NN * DD];   // x_agg_emb
__device__ float d_gsum[GG * DD];
__device__ int   d_gcnt[GG];
__device__ float d_rg[GG * DD];        // relu(g_agg @ W_g + b_g)

// ---------------- setup -----------------------------------------------------

__global__ void k_detect_zero(const long long* __restrict__ ei) {
    int i = blockIdx.x * blockDim.x + threadIdx.x;
    int st = gridDim.x * blockDim.x;
    if (i < EE) {
        long long v = ei[i];
        if (v < 0 || v >= NN) d_is64 = 0;
    }
    for (int j = i; j < NN; j += st) d_deg[j] = 0;
    if (i < GG) { d_degmaxbits[i] = 0; d_gcnt[i] = 0; }
    if (i < GG * DD) d_gsum[i] = 0.f;
}

__global__ void k_cvt_count(const void* __restrict__ ei, const void* __restrict__ bt,
                            const float* __restrict__ degree) {
    __shared__ int smax[GG];
    int i = blockIdx.x * blockDim.x + threadIdx.x;
    int t = threadIdx.x;
    int s = d_is64;
    bool node_blk = (blockIdx.x * blockDim.x) < NN;
    if (node_blk) {
        if (t < GG) smax[t] = 0;
        __syncthreads();
    }
    if (i < EE) {
        int r = s ? (int)((const long long*)ei)[EE + i] : ((const int*)ei)[EE + i];
        atomicAdd(&d_deg[r], 1);
    }
    if (i < NN) {
        int b = s ? (int)((const long long*)bt)[i] : ((const int*)bt)[i];
        d_batch[i] = b;
        atomicMax(&smax[b], __float_as_int(degree[i]));
    }
    if (node_blk) {
        __syncthreads();
        if (t < GG && smax[t] != 0) atomicMax(&d_degmaxbits[t], smax[t]);
    }
}

__global__ void k_bsum() {
    __shared__ int s[SCAN_B];
    int t = threadIdx.x;
    int i = blockIdx.x * SCAN_B + t;
    s[t] = (i < NN) ? d_deg[i] : 0;
    __syncthreads();
    for (int off = SCAN_B / 2; off; off >>= 1) {
        if (t < off) s[t] += s[t + off];
        __syncthreads();
    }
    if (t == 0) d_bsum[blockIdx.x] = s[0];
}

__global__ void k_pscan() {
    __shared__ int sb[SCAN_B];
    __shared__ int s[SCAN_B];
    int t = threadIdx.x;
    sb[t] = (t < NSB) ? d_bsum[t] : 0;
    int i = blockIdx.x * SCAN_B + t;
    int v = (i < NN) ? d_deg[i] : 0;
    s[t] = v;
    __syncthreads();
    for (int off = 1; off < SCAN_B; off <<= 1) {
        int a = (t >= off) ? sb[t - off] : 0;
        int b = (t >= off) ? s[t - off] : 0;
        __syncthreads();
        sb[t] += a;
        s[t] += b;
        __syncthreads();
    }
    int boff = (blockIdx.x == 0) ? 0 : sb[blockIdx.x - 1];
    int excl = s[t] - v + boff;
    if (i < NN) { d_rowptr[i] = excl; d_cursor[i] = excl; }
    if (i == 0) d_rowptr[NN] = EE;
}

__global__ void k_fill(const void* __restrict__ ei, const float* __restrict__ ea) {
    int e = blockIdx.x * blockDim.x + threadIdx.x;
    if (e >= EE) return;
    int s = d_is64;
    int c = s ? (int)((const long long*)ei)[e]      : ((const int*)ei)[e];
    int r = s ? (int)((const long long*)ei)[EE + e] : ((const int*)ei)[EE + e];
    int p = atomicAdd(&d_cursor[r], 1);
    d_csr[p] = make_int2(c, __float_as_int(ea[e]));
}

// ---------------- embeddings -------------------------------------------------

__global__ void k_xemb(const float* __restrict__ x, const float* __restrict__ W,
                       const float* __restrict__ b) {
    int i = blockIdx.x * blockDim.x + threadIdx.x;
    if (i >= NN * DD) return;
    int n = i >> 6, c = i & 63;
    const float* xr = x + n * 7;
    float s = b[c];
#pragma unroll
    for (int k = 0; k < 7; k++) s += xr[k] * W[k * DD + c];
    d_e0[i] = fmaxf(s, 0.f);
}

__global__ void k_ne(const float* __restrict__ x, const float* __restrict__ W,
                     const float* __restrict__ b) {
    int warp = (blockIdx.x * blockDim.x + threadIdx.x) >> 5;
    int lane = threadIdx.x & 31;
    if (warp >= NN) return;
    int n = warp;
    int beg = d_rowptr[n], end = d_rowptr[n + 1];
    float acc[8] = {0, 0, 0, 0, 0, 0, 0, 0};
    for (int j = beg + lane; j < end; j += 32) {
        int2 cv = d_csr[j];
        const float* xr = x + cv.x * 7;
#pragma unroll
        for (int k = 0; k < 7; k++) acc[k] += xr[k];
        acc[7] += __int_as_float(cv.y);
    }
#pragma unroll
    for (int k = 0; k < 8; k++)
#pragma unroll
        for (int off = 16; off; off >>= 1) acc[k] += __shfl_xor_sync(0xffffffffu, acc[k], off);
    float inv = 1.f / (float)max(end - beg, 1);
#pragma unroll
    for (int k = 0; k < 8; k++) acc[k] *= inv;
    float o0 = b[lane];
    float o1 = (lane < 31) ? b[lane + 32] : 0.f;
#pragma unroll
    for (int k = 0; k < 8; k++) {
        o0 += acc[k] * W[k * 63 + lane];
        if (lane < 31) o1 += acc[k] * W[k * 63 + lane + 32];
    }
    d_nein[n * DD + lane] = fmaxf(o0, 0.f);
    if (lane < 31) d_nein[n * DD + 32 + lane] = fmaxf(o1, 0.f);
    if (lane == 31) d_nein[n * DD + 63] = __int_as_float(d_degmaxbits[d_batch[n]]);
}

__global__ void k_aggemb(const float* __restrict__ W, const float* __restrict__ b) {
    int i = blockIdx.x * blockDim.x + threadIdx.x;
    if (i >= NN * DD) return;
    int n = i >> 6, c = i & 63;
    const float* in = d_nein + n * DD;
    float s = b[c];
#pragma unroll
    for (int k = 0; k < DD; k++) s += in[k] * W[k * DD + c];
    d_xaggemb[i] = fmaxf(s, 0.f);
}

// ---------------- edge gather (split; full occupancy, 4 load chains) ---------
__global__ void __launch_bounds__(256) k_gather(int flip) {
    const float* xin = flip ? d_e1 : d_e0;
    int warp = (blockIdx.x * blockDim.x + threadIdx.x) >> 5;
    int lane = threadIdx.x & 31;
    if (warp >= NN) return;
    int n = warp;
    int beg = d_rowptr[n], end = d_rowptr[n + 1];
    float a0 = 0.f, a1 = 0.f, b0 = 0.f, b1 = 0.f;
    float c0 = 0.f, c1 = 0.f, e0 = 0.f, e1 = 0.f;
    int j = beg;
    for (; j + 3 < end; j += 4) {
        int2 v0 = d_csr[j],     v1 = d_csr[j + 1];
        int2 v2 = d_csr[j + 2], v3 = d_csr[j + 3];
        const float* r0 = xin + v0.x * DD;
        const float* r1 = xin + v1.x * DD;
        const float* r2 = xin + v2.x * DD;
        const float* r3 = xin + v3.x * DD;
        float w0 = __int_as_float(v0.y), w1 = __int_as_float(v1.y);
        float w2 = __int_as_float(v2.y), w3 = __int_as_float(v3.y);
        a0 += w0 * r0[lane]; a1 += w0 * r0[lane + 32];
        b0 += w1 * r1[lane]; b1 += w1 * r1[lane + 32];
        c0 += w2 * r2[lane]; c1 += w2 * r2[lane + 32];
        e0 += w3 * r3[lane]; e1 += w3 * r3[lane + 32];
    }
    for (; j < end; j++) {
        int2 v = d_csr[j];
        const float* r = xin + v.x * DD;
        float w = __int_as_float(v.y);
        a0 += w * r[lane]; a1 += w * r[lane + 32];
    }
    float inv = 1.f / (float)max(end - beg, 1);
    d_xagg[n * DD + lane]      = (a0 + b0 + c0 + e0) * inv;
    d_xagg[n * DD + 32 + lane] = (a1 + b1 + c1 + e1) * inv;
}

// ---------------- message-passing MLP (gather removed) -----------------------
#define NPW 4
#define TBL 512
#define WPB 16
#define LAYER_SMEM ((8192 + 8192 + WPB * NPW * 128) * (int)sizeof(float))

__global__ void __launch_bounds__(TBL) k_layer(
    int flip,   // 0: e0 -> e1 ; 1: e1 -> e0
    const float* __restrict__ Wm, const float* __restrict__ bm,
    const float* __restrict__ Wu, const float* __restrict__ bu) {
    const float* xin  = flip ? d_e1 : d_e0;
    float*       xout = flip ? d_e0 : d_e1;
    extern __shared__ float sm[];
    float* sWm = sm;
    float* sWu = sm + 8192;
    float* sIn = sm + 16384;
    int t = threadIdx.x;
    for (int i = t; i < 8192; i += TBL) { sWm[i] = Wm[i]; sWu[i] = Wu[i]; }
    __syncthreads();

    int warp = t >> 5, lane = t & 31;
    float* sv = sIn + warp * (NPW * 128);           // [k in 0..127][i in 0..3]
    const float4* sv4 = (const float4*)sv;
    int nbase = blockIdx.x * (WPB * NPW) + warp * NPW;

    // Phase A': load staged gather + x_agg_emb (coalesced)
#pragma unroll
    for (int i = 0; i < NPW; i++) {
        int n = nbase + i;
        float a0 = 0.f, a1 = 0.f, g0 = 0.f, g1 = 0.f;
        if (n < NN) {
            a0 = d_xagg[n * DD + lane];
            a1 = d_xagg[n * DD + 32 + lane];
            g0 = d_xaggemb[n * DD + lane];
            g1 = d_xaggemb[n * DD + 32 + lane];
        }
        sv[lane * 4 + i]        = a0;
        sv[(lane + 32) * 4 + i] = a1;
        sv[(lane + 64) * 4 + i] = g0;
        sv[(lane + 96) * 4 + i] = g1;
    }
    __syncwarp();

    // Phase B: m = relu([x_agg, x_agg_emb] @ Wm + bm)
    float m0[NPW], m1[NPW];
    {
        float b0 = bm[lane], b1 = bm[lane + 32];
#pragma unroll
        for (int i = 0; i < NPW; i++) { m0[i] = b0; m1[i] = b1; }
    }
#pragma unroll 4
    for (int k = 0; k < 128; k++) {
        float w0 = sWm[k * DD + lane];
        float w1 = sWm[k * DD + lane + 32];
        float4 v = sv4[k];
        m0[0] += v.x * w0; m1[0] += v.x * w1;
        m0[1] += v.y * w0; m1[1] += v.y * w1;
        m0[2] += v.z * w0; m1[2] += v.z * w1;
        m0[3] += v.w * w0; m1[3] += v.w * w1;
    }
    __syncwarp();

    // Phase C: stage [x_emb_old, relu(m)]
#pragma unroll
    for (int i = 0; i < NPW; i++) {
        int n = nbase + i;
        float x0 = 0.f, x1 = 0.f;
        if (n < NN) {
            x0 = xin[n * DD + lane];
            x1 = xin[n * DD + 32 + lane];
        }
        sv[lane * 4 + i]        = x0;
        sv[(lane + 32) * 4 + i] = x1;
        sv[(lane + 64) * 4 + i] = fmaxf(m0[i], 0.f);
        sv[(lane + 96) * 4 + i] = fmaxf(m1[i], 0.f);
    }
    __syncwarp();

    // Phase D: x_emb_new = relu([x_emb, m] @ Wu + bu)
    float u0[NPW], u1[NPW];
    {
        float b0 = bu[lane], b1 = bu[lane + 32];
#pragma unroll
        for (int i = 0; i < NPW; i++) { u0[i] = b0; u1[i] = b1; }
    }
#pragma unroll 4
    for (int k = 0; k < 128; k++) {
        float w0 = sWu[k * DD + lane];
        float w1 = sWu[k * DD + lane + 32];
        float4 v = sv4[k];
        u0[0] += v.x * w0; u1[0] += v.x * w1;
        u0[1] += v.y * w0; u1[1] += v.y * w1;
        u0[2] += v.z * w0; u1[2] += v.z * w1;
        u0[3] += v.w * w0; u1[3] += v.w * w1;
    }
#pragma unroll
    for (int i = 0; i < NPW; i++) {
        int n = nbase + i;
        if (n < NN) {
            xout[n * DD + lane]      = fmaxf(u0[i], 0.f);
            xout[n * DD + 32 + lane] = fmaxf(u1[i], 0.f);
        }
    }
}

// ---------------- readout ----------------------------------------------------

__global__ void k_gsum() {
    __shared__ float sg[GG * DD];
    __shared__ int sc[GG];
    int t = threadIdx.x;
    for (int i = t; i < GG * DD; i += blockDim.x) sg[i] = 0.f;
    for (int i = t; i < GG; i += blockDim.x) sc[i] = 0;
    __syncthreads();
    int per = (NN + gridDim.x - 1) / gridDim.x;
    int nb = blockIdx.x * per;
    int ne = min(NN, nb + per);
    int col = t & 63, sub = t >> 6;
    for (int n = nb + sub; n < ne; n += 4) {
        int g = d_batch[n];
        atomicAdd(&sg[g * DD + col], d_e1[n * DD + col]);
        if (col == 0) atomicAdd(&sc[g], 1);
    }
    __syncthreads();
    for (int i = t; i < GG * DD; i += blockDim.x) atomicAdd(&d_gsum[i], sg[i]);
    for (int i = t; i < GG; i += blockDim.x) atomicAdd(&d_gcnt[i], sc[i]);
}

__global__ void k_gproj(const float* __restrict__ Wg, const float* __restrict__ bg) {
    int g = blockIdx.x, c = threadIdx.x;
    float inv = 1.f / (float)max(d_gcnt[g], 1);
    float s = bg[c];
    const float* row = d_gsum + g * DD;
#pragma unroll
    for (int k = 0; k < DD; k++) s += row[k] * inv * Wg[k * DD + c];
    d_rg[g * DD + c] = fmaxf(s, 0.f);
}

__global__ void k_final(const float* __restrict__ Wr, const float* __restrict__ br,
                        float* __restrict__ out) {
    int warp = (blockIdx.x * blockDim.x + threadIdx.x) >> 5;
    int lane = threadIdx.x & 31;
    if (warp >= NN) return;
    int n = warp;
    int g = d_batch[n];
    const float* rg = d_rg + g * DD;
    const float* xr = d_e1 + n * DD;
    float p = rg[lane] * Wr[lane] + rg[lane + 32] * Wr[lane + 32]
            + xr[lane] * Wr[64 + lane] + xr[lane + 32] * Wr[96 + lane];
#pragma unroll
    for (int off = 16; off; off >>= 1) p += __shfl_xor_sync(0xffffffffu, p, off);
    if (lane == 0) out[n] = p + br[0];
}

// ---------------- launch ------------------------------------------------------

extern "C" void kernel_launch(void* const* d_in, const int* in_sizes, int n_in,
                              void* d_out, int out_size) {
    int base = (n_in > 5 && in_sizes[5] == 1) ? 6 : 5;

    const float* x      = (const float*)d_in[0];
    const void*  ei     = d_in[1];
    const float* ea     = (const float*)d_in[2];
    const void*  batch  = d_in[3];
    const float* degree = (const float*)d_in[4];
    const float* W_en  = (const float*)d_in[base + 0];
    const float* b_en  = (const float*)d_in[base + 1];
    const float* W_ene = (const float*)d_in[base + 2];
    const float* b_ene = (const float*)d_in[base + 3];
    const float* W_agg = (const float*)d_in[base + 4];
    const float* b_agg = (const float*)d_in[base + 5];
    const float* Wm    = (const float*)d_in[base + 6];
    const float* bm    = (const float*)d_in[base + 7];
    const float* Wu    = (const float*)d_in[base + 8];
    const float* bu    = (const float*)d_in[base + 9];
    const float* W_g   = (const float*)d_in[base + 10];
    const float* b_g   = (const float*)d_in[base + 11];
    const float* W_r   = (const float*)d_in[base + 12];
    const float* b_r   = (const float*)d_in[base + 13];
    float* out = (float*)d_out;

    cudaFuncSetAttribute(k_layer, cudaFuncAttributeMaxDynamicSharedMemorySize, LAYER_SMEM);

    const int TB = 256;
    int gE  = (EE + TB - 1) / TB;
    int gND = (NN * DD + TB - 1) / TB;
    int gNW = (NN * 32 + TB - 1) / TB;

    k_xemb<<<gND, TB>>>(x, W_en, b_en);
    k_detect_zero<<<gE, TB>>>((const long long*)ei);
    k_cvt_count<<<gE, TB>>>(ei, batch, degree);
    k_bsum<<<NSB, SCAN_B>>>();
    k_pscan<<<NSB, SCAN_B>>>();
    k_fill<<<gE, TB>>>(ei, ea);

    k_ne<<<gNW, TB>>>(x, W_ene, b_ene);
    k_aggemb<<<gND, TB>>>(W_agg, b_agg);

    int nodes_per_blk = WPB * NPW;   // 64
    int gL = (NN + nodes_per_blk - 1) / nodes_per_blk;   // 782
    // layer 0: e0 -> e1 ; layer 1: e1 -> e0 ; layer 2: e0 -> e1
    k_gather<<<gNW, TB>>>(0);
    k_layer<<<gL, TBL, LAYER_SMEM>>>(0, Wm + 0 * 8192, bm + 0 * 64, Wu + 0 * 8192, bu + 0 * 64);
    k_gather<<<gNW, TB>>>(1);
    k_layer<<<gL, TBL, LAYER_SMEM>>>(1, Wm + 1 * 8192, bm + 1 * 64, Wu + 1 * 8192, bu + 1 * 64);
    k_gather<<<gNW, TB>>>(0);
    k_layer<<<gL, TBL, LAYER_SMEM>>>(0, Wm + 2 * 8192, bm + 2 * 64, Wu + 2 * 8192, bu + 2 * 64);

    k_gsum<<<148, TB>>>();
    k_gproj<<<GG, DD>>>(W_g, b_g);
    k_final<<<gNW, TB>>>(W_r, b_r, out);

    (void)in_sizes; (void)n_in; (void)out_size; (void)degree;
}

// round 17
// speedup vs baseline: 1.0117x; 1.0117x over previous
#include <cuda_runtime.h>

#define NN 50000
#define EE 800000
#define DD 64
#define GG 64

#define SCAN_B 256
#define NSB ((NN + SCAN_B - 1) / SCAN_B)   // 196 blocks

// ---------------- scratch (device globals; accessed ONLY by symbol in device code)
__device__ int   d_is64 = 1;           // write-once 1->0 (deterministic across replays)
__device__ int   d_batch[NN];
__device__ int   d_deg[NN];
__device__ int   d_rowptr[NN + 1];
__device__ int   d_cursor[NN];
__device__ int2  d_csr[EE];            // (col, edge_attr float bits)
__device__ int   d_bsum[NSB];
__device__ int   d_degmaxbits[GG];     // per-graph max degree, float bits (degree >= 0)
__device__ float d_e0[NN * DD];        // x_emb ping
__device__ float d_e1[NN * DD];        // x_emb pong
__device__ float d_nein[NN * DD];      // [0:62] relu node_edge embed, [63] degree_norm
__device__ float d_xaggemb[NN * DD];   // x_agg_emb
__device__ float d_gsum[GG * DD];
__device__ int   d_gcnt[GG];
__device__ float d_rg[GG * DD];        // relu(g_agg @ W_g + b_g)

// ---------------- setup -----------------------------------------------------

// per-launch zeroing + int64/int32 sniff over the first 65536 elements.
// int32 data read as int64 has a random node index in the high 32 bits;
// P(all 32k high-words == 0) is numerically zero, so 64k elements decide it.
#define SNIFF 65536
__global__ void k_detect_zero(const long long* __restrict__ ei) {
    int i = blockIdx.x * blockDim.x + threadIdx.x;
    int st = gridDim.x * blockDim.x;   // 64*256 = 16384
    for (int j = i; j < SNIFF; j += st) {
        long long v = ei[j];
        if (v < 0 || v >= NN) d_is64 = 0;
    }
    for (int j = i; j < NN; j += st) d_deg[j] = 0;
    if (i < GG) { d_degmaxbits[i] = 0; d_gcnt[i] = 0; }
    if (i < GG * DD) d_gsum[i] = 0.f;
}

// fused: in-degree histogram (ILP x4) + batch convert + smem-staged degmax.
// 4 independent edge loads per thread -> MLP_eff ~4 (was 1).
__global__ void k_cvt_count(const void* __restrict__ ei, const void* __restrict__ bt,
                            const float* __restrict__ degree) {
    __shared__ int smax[GG];
    int t = threadIdx.x;
    int s = d_is64;
    bool node_blk = (blockIdx.x * blockDim.x) < NN;
    if (node_blk) {
        if (t < GG) smax[t] = 0;
        __syncthreads();
    }
    int ebase = blockIdx.x * (blockDim.x * 4) + t;
    int r[4];
#pragma unroll
    for (int k = 0; k < 4; k++) {
        int e = ebase + k * 256;
        r[k] = (e < EE) ? (s ? (int)((const long long*)ei)[EE + e]
                             : ((const int*)ei)[EE + e]) : -1;
    }
#pragma unroll
    for (int k = 0; k < 4; k++)
        if (r[k] >= 0) atomicAdd(&d_deg[r[k]], 1);

    int i = blockIdx.x * blockDim.x + t;
    if (i < NN) {
        int b = s ? (int)((const long long*)bt)[i] : ((const int*)bt)[i];
        d_batch[i] = b;
        atomicMax(&smax[b], __float_as_int(degree[i]));
    }
    if (node_blk) {
        __syncthreads();
        if (t < GG && smax[t] != 0) atomicMax(&d_degmaxbits[t], smax[t]);
    }
}

// ---- parallel exclusive scan of d_deg ----

__global__ void k_bsum() {
    __shared__ int s[SCAN_B];
    int t = threadIdx.x;
    int i = blockIdx.x * SCAN_B + t;
    s[t] = (i < NN) ? d_deg[i] : 0;
    __syncthreads();
    for (int off = SCAN_B / 2; off; off >>= 1) {
        if (t < off) s[t] += s[t + off];
        __syncthreads();
    }
    if (t == 0) d_bsum[blockIdx.x] = s[0];
}

__global__ void k_pscan() {
    __shared__ int sb[SCAN_B];
    __shared__ int s[SCAN_B];
    int t = threadIdx.x;
    sb[t] = (t < NSB) ? d_bsum[t] : 0;
    int i = blockIdx.x * SCAN_B + t;
    int v = (i < NN) ? d_deg[i] : 0;
    s[t] = v;
    __syncthreads();
    for (int off = 1; off < SCAN_B; off <<= 1) {
        int a = (t >= off) ? sb[t - off] : 0;
        int b = (t >= off) ? s[t - off] : 0;
        __syncthreads();
        sb[t] += a;
        s[t] += b;
        __syncthreads();
    }
    int boff = (blockIdx.x == 0) ? 0 : sb[blockIdx.x - 1];
    int excl = s[t] - v + boff;
    if (i < NN) { d_rowptr[i] = excl; d_cursor[i] = excl; }
    if (i == 0) d_rowptr[NN] = EE;
}

// CSR fill, ILP x4: batch 4 (col,row,ea) loads, then 4 atomic+store pairs.
__global__ void k_fill(const void* __restrict__ ei, const float* __restrict__ ea) {
    int t = threadIdx.x;
    int s = d_is64;
    int ebase = blockIdx.x * (blockDim.x * 4) + t;
    int c[4], r[4]; float v[4];
#pragma unroll
    for (int k = 0; k < 4; k++) {
        int e = ebase + k * 256;
        if (e < EE) {
            c[k] = s ? (int)((const long long*)ei)[e]      : ((const int*)ei)[e];
            r[k] = s ? (int)((const long long*)ei)[EE + e] : ((const int*)ei)[EE + e];
            v[k] = ea[e];
        } else r[k] = -1;
    }
#pragma unroll
    for (int k = 0; k < 4; k++) {
        if (r[k] >= 0) {
            int p = atomicAdd(&d_cursor[r[k]], 1);
            d_csr[p] = make_int2(c[k], __float_as_int(v[k]));
        }
    }
}

// ---------------- embeddings -------------------------------------------------

__global__ void k_xemb(const float* __restrict__ x, const float* __restrict__ W,
                       const float* __restrict__ b) {
    int i = blockIdx.x * blockDim.x + threadIdx.x;
    if (i >= NN * DD) return;
    int n = i >> 6, c = i & 63;
    const float* xr = x + n * 7;
    float s = b[c];
#pragma unroll
    for (int k = 0; k < 7; k++) s += xr[k] * W[k * DD + c];
    d_e0[i] = fmaxf(s, 0.f);
}

__global__ void k_ne(const float* __restrict__ x, const float* __restrict__ W,
                     const float* __restrict__ b) {
    int warp = (blockIdx.x * blockDim.x + threadIdx.x) >> 5;
    int lane = threadIdx.x & 31;
    if (warp >= NN) return;
    int n = warp;
    int beg = d_rowptr[n], end = d_rowptr[n + 1];
    float acc[8] = {0, 0, 0, 0, 0, 0, 0, 0};
    for (int j = beg + lane; j < end; j += 32) {
        int2 cv = d_csr[j];
        const float* xr = x + cv.x * 7;
#pragma unroll
        for (int k = 0; k < 7; k++) acc[k] += xr[k];
        acc[7] += __int_as_float(cv.y);
    }
#pragma unroll
    for (int k = 0; k < 8; k++)
#pragma unroll
        for (int off = 16; off; off >>= 1) acc[k] += __shfl_xor_sync(0xffffffffu, acc[k], off);
    float inv = 1.f / (float)max(end - beg, 1);
#pragma unroll
    for (int k = 0; k < 8; k++) acc[k] *= inv;
    float o0 = b[lane];
    float o1 = (lane < 31) ? b[lane + 32] : 0.f;
#pragma unroll
    for (int k = 0; k < 8; k++) {
        o0 += acc[k] * W[k * 63 + lane];
        if (lane < 31) o1 += acc[k] * W[k * 63 + lane + 32];
    }
    d_nein[n * DD + lane] = fmaxf(o0, 0.f);
    if (lane < 31) d_nein[n * DD + 32 + lane] = fmaxf(o1, 0.f);
    if (lane == 31) d_nein[n * DD + 63] = __int_as_float(d_degmaxbits[d_batch[n]]);
}

__global__ void k_aggemb(const float* __restrict__ W, const float* __restrict__ b) {
    int i = blockIdx.x * blockDim.x + threadIdx.x;
    if (i >= NN * DD) return;
    int n = i >> 6, c = i & 63;
    const float* in = d_nein + n * DD;
    float s = b[c];
#pragma unroll
    for (int k = 0; k < DD; k++) s += in[k] * W[k * DD + c];
    d_xaggemb[i] = fmaxf(s, 0.f);
}

// ---------------- fused message-passing layer (R13 proven; best measured) ----
// 512 thr = 16 warps (8 warps/SMSP at 2 blocks/SM), warp owns 4 nodes;
// Phase A dual-chain gather; staging [k][node] -> LDS.128 broadcast in MLPs.
// dyn smem: Wm 32KB + Wu 32KB + staging 16 warps * 2KB = 96KB

#define NPW 4
#define TBL 512
#define WPB 16
#define LAYER_SMEM ((8192 + 8192 + WPB * NPW * 128) * (int)sizeof(float))

__global__ void __launch_bounds__(TBL) k_layer(
    int flip,   // 0: e0 -> e1 ; 1: e1 -> e0
    const float* __restrict__ Wm, const float* __restrict__ bm,
    const float* __restrict__ Wu, const float* __restrict__ bu) {
    const float* xin  = flip ? d_e1 : d_e0;
    float*       xout = flip ? d_e0 : d_e1;
    extern __shared__ float sm[];
    float* sWm = sm;
    float* sWu = sm + 8192;
    float* sIn = sm + 16384;
    int t = threadIdx.x;
    for (int i = t; i < 8192; i += TBL) { sWm[i] = Wm[i]; sWu[i] = Wu[i]; }
    __syncthreads();

    int warp = t >> 5, lane = t & 31;
    float* sv = sIn + warp * (NPW * 128);           // [k in 0..127][i in 0..3]
    const float4* sv4 = (const float4*)sv;
    int nbase = blockIdx.x * (WPB * NPW) + warp * NPW;

    // Phase A: x_agg = mean_{e->n} ea[e]*xin[col[e]]; stage [x_agg, x_agg_emb]
#pragma unroll
    for (int i = 0; i < NPW; i++) {
        int n = nbase + i;
        float a0 = 0.f, a1 = 0.f, g0 = 0.f, g1 = 0.f;
        if (n < NN) {
            int beg = d_rowptr[n], end = d_rowptr[n + 1];
            float c0 = 0.f, c1 = 0.f;       // second chain
            int j = beg;
            for (; j + 1 < end; j += 2) {
                int2 cva = d_csr[j];
                int2 cvb = d_csr[j + 1];
                float wa = __int_as_float(cva.y);
                float wb = __int_as_float(cvb.y);
                const float* xra = xin + cva.x * DD;
                const float* xrb = xin + cvb.x * DD;
                a0 += wa * xra[lane];
                a1 += wa * xra[lane + 32];
                c0 += wb * xrb[lane];
                c1 += wb * xrb[lane + 32];
            }
            if (j < end) {
                int2 cv = d_csr[j];
                float w = __int_as_float(cv.y);
                const float* xr = xin + cv.x * DD;
                a0 += w * xr[lane];
                a1 += w * xr[lane + 32];
            }
            a0 += c0; a1 += c1;
            float inv = 1.f / (float)max(end - beg, 1);
            a0 *= inv; a1 *= inv;
            g0 = d_xaggemb[n * DD + lane];
            g1 = d_xaggemb[n * DD + 32 + lane];
        }
        sv[lane * 4 + i]        = a0;
        sv[(lane + 32) * 4 + i] = a1;
        sv[(lane + 64) * 4 + i] = g0;
        sv[(lane + 96) * 4 + i] = g1;
    }
    __syncwarp();

    // Phase B: m = relu([x_agg, x_agg_emb] @ Wm + bm)
    float m0[NPW], m1[NPW];
    {
        float b0 = bm[lane], b1 = bm[lane + 32];
#pragma unroll
        for (int i = 0; i < NPW; i++) { m0[i] = b0; m1[i] = b1; }
    }
#pragma unroll 4
    for (int k = 0; k < 128; k++) {
        float w0 = sWm[k * DD + lane];
        float w1 = sWm[k * DD + lane + 32];
        float4 v = sv4[k];
        m0[0] += v.x * w0; m1[0] += v.x * w1;
        m0[1] += v.y * w0; m1[1] += v.y * w1;
        m0[2] += v.z * w0; m1[2] += v.z * w1;
        m0[3] += v.w * w0; m1[3] += v.w * w1;
    }
    __syncwarp();

    // Phase C: stage [x_emb_old, relu(m)]
#pragma unroll
    for (int i = 0; i < NPW; i++) {
        int n = nbase + i;
        float x0 = 0.f, x1 = 0.f;
        if (n < NN) {
            x0 = xin[n * DD + lane];
            x1 = xin[n * DD + 32 + lane];
        }
        sv[lane * 4 + i]        = x0;
        sv[(lane + 32) * 4 + i] = x1;
        sv[(lane + 64) * 4 + i] = fmaxf(m0[i], 0.f);
        sv[(lane + 96) * 4 + i] = fmaxf(m1[i], 0.f);
    }
    __syncwarp();

    // Phase D: x_emb_new = relu([x_emb, m] @ Wu + bu)
    float u0[NPW], u1[NPW];
    {
        float b0 = bu[lane], b1 = bu[lane + 32];
#pragma unroll
        for (int i = 0; i < NPW; i++) { u0[i] = b0; u1[i] = b1; }
    }
#pragma unroll 4
    for (int k = 0; k < 128; k++) {
        float w0 = sWu[k * DD + lane];
        float w1 = sWu[k * DD + lane + 32];
        float4 v = sv4[k];
        u0[0] += v.x * w0; u1[0] += v.x * w1;
        u0[1] += v.y * w0; u1[1] += v.y * w1;
        u0[2] += v.z * w0; u1[2] += v.z * w1;
        u0[3] += v.w * w0; u1[3] += v.w * w1;
    }
#pragma unroll
    for (int i = 0; i < NPW; i++) {
        int n = nbase + i;
        if (n < NN) {
            xout[n * DD + lane]      = fmaxf(u0[i], 0.f);
            xout[n * DD + 32 + lane] = fmaxf(u1[i], 0.f);
        }
    }
}

// ---------------- readout ----------------------------------------------------

__global__ void k_gsum() {
    __shared__ float sg[GG * DD];
    __shared__ int sc[GG];
    int t = threadIdx.x;
    for (int i = t; i < GG * DD; i += blockDim.x) sg[i] = 0.f;
    for (int i = t; i < GG; i += blockDim.x) sc[i] = 0;
    __syncthreads();
    int per = (NN + gridDim.x - 1) / gridDim.x;
    int nb = blockIdx.x * per;
    int ne = min(NN, nb + per);
    int col = t & 63, sub = t >> 6;
    for (int n = nb + sub; n < ne; n += 4) {
        int g = d_batch[n];
        atomicAdd(&sg[g * DD + col], d_e1[n * DD + col]);
        if (col == 0) atomicAdd(&sc[g], 1);
    }
    __syncthreads();
    for (int i = t; i < GG * DD; i += blockDim.x) atomicAdd(&d_gsum[i], sg[i]);
    for (int i = t; i < GG; i += blockDim.x) atomicAdd(&d_gcnt[i], sc[i]);
}

__global__ void k_gproj(const float* __restrict__ Wg, const float* __restrict__ bg) {
    int g = blockIdx.x, c = threadIdx.x;
    float inv = 1.f / (float)max(d_gcnt[g], 1);
    float s = bg[c];
    const float* row = d_gsum + g * DD;
#pragma unroll
    for (int k = 0; k < DD; k++) s += row[k] * inv * Wg[k * DD + c];
    d_rg[g * DD + c] = fmaxf(s, 0.f);
}

__global__ void k_final(const float* __restrict__ Wr, const float* __restrict__ br,
                        float* __restrict__ out) {
    int warp = (blockIdx.x * blockDim.x + threadIdx.x) >> 5;
    int lane = threadIdx.x & 31;
    if (warp >= NN) return;
    int n = warp;
    int g = d_batch[n];
    const float* rg = d_rg + g * DD;
    const float* xr = d_e1 + n * DD;
    float p = rg[lane] * Wr[lane] + rg[lane + 32] * Wr[lane + 32]
            + xr[lane] * Wr[64 + lane] + xr[lane + 32] * Wr[96 + lane];
#pragma unroll
    for (int off = 16; off; off >>= 1) p += __shfl_xor_sync(0xffffffffu, p, off);
    if (lane == 0) out[n] = p + br[0];
}

// ---------------- launch ------------------------------------------------------

extern "C" void kernel_launch(void* const* d_in, const int* in_sizes, int n_in,
                              void* d_out, int out_size) {
    int base = (n_in > 5 && in_sizes[5] == 1) ? 6 : 5;

    const float* x      = (const float*)d_in[0];
    const void*  ei     = d_in[1];
    const float* ea     = (const float*)d_in[2];
    const void*  batch  = d_in[3];
    const float* degree = (const float*)d_in[4];
    const float* W_en  = (const float*)d_in[base + 0];
    const float* b_en  = (const float*)d_in[base + 1];
    const float* W_ene = (const float*)d_in[base + 2];
    const float* b_ene = (const float*)d_in[base + 3];
    const float* W_agg = (const float*)d_in[base + 4];
    const float* b_agg = (const float*)d_in[base + 5];
    const float* Wm    = (const float*)d_in[base + 6];
    const float* bm    = (const float*)d_in[base + 7];
    const float* Wu    = (const float*)d_in[base + 8];
    const float* bu    = (const float*)d_in[base + 9];
    const float* W_g   = (const float*)d_in[base + 10];
    const float* b_g   = (const float*)d_in[base + 11];
    const float* W_r   = (const float*)d_in[base + 12];
    const float* b_r   = (const float*)d_in[base + 13];
    float* out = (float*)d_out;

    cudaFuncSetAttribute(k_layer, cudaFuncAttributeMaxDynamicSharedMemorySize, LAYER_SMEM);

    const int TB = 256;
    int gE4 = (EE + TB * 4 - 1) / (TB * 4);   // 782 blocks, 4 edges/thread
    int gND = (NN * DD + TB - 1) / TB;
    int gNW = (NN * 32 + TB - 1) / TB;

    k_xemb<<<gND, TB>>>(x, W_en, b_en);
    k_detect_zero<<<64, TB>>>((const long long*)ei);
    k_cvt_count<<<gE4, TB>>>(ei, batch, degree);
    k_bsum<<<NSB, SCAN_B>>>();
    k_pscan<<<NSB, SCAN_B>>>();
    k_fill<<<gE4, TB>>>(ei, ea);

    k_ne<<<gNW, TB>>>(x, W_ene, b_ene);
    k_aggemb<<<gND, TB>>>(W_agg, b_agg);

    int nodes_per_blk = WPB * NPW;   // 64
    int gL = (NN + nodes_per_blk - 1) / nodes_per_blk;   // 782
    k_layer<<<gL, TBL, LAYER_SMEM>>>(0, Wm + 0 * 8192, bm + 0 * 64, Wu + 0 * 8192, bu + 0 * 64);
    k_layer<<<gL, TBL, LAYER_SMEM>>>(1, Wm + 1 * 8192, bm + 1 * 64, Wu + 1 * 8192, bu + 1 * 64);
    k_layer<<<gL, TBL, LAYER_SMEM>>>(0, Wm + 2 * 8192, bm + 2 * 64, Wu + 2 * 8192, bu + 2 * 64);

    k_gsum<<<148, TB>>>();
    k_gproj<<<GG, DD>>>(W_g, b_g);
    k_final<<<gNW, TB>>>(W_r, b_r, out);

    (void)in_sizes; (void)n_in; (void)out_size; (void)degree;
}